// round 10
// baseline (speedup 1.0000x reference)
#include <cuda_runtime.h>
#include <cuda_fp16.h>
#include <math.h>
#include <stdint.h>

// Shapes (fixed by the problem)
#define NB   16
#define CCH  256
#define HH   32
#define WW   32
#define LL   (HH*WW)       // 1024
#define PP   2048
#define KEEP 102           // int(0.05 * 2048)
#define K3   768           // 3x fp16 split K (h | l*64 | h/64) . (h | h/64 | l*64)

// ---------------------------------------------------------------------------
// Scratch (device globals only; no allocations allowed)
// ---------------------------------------------------------------------------
__device__ float  g_invxn[NB * LL];                    // 64 KB
__device__ __half g_A[(size_t)NB * LL * K3];           // 25 MB  A' split of x^T * invxn
__device__ __half g_B[(size_t)PP * K3];                // 3 MB   B' split of poolN
__device__ float  g_cos[(size_t)NB * LL * PP];         // 134 MB

// ---------------------------------------------------------------------------
// Kernel 1: normalize pool rows, write fp16 split B' = [h | h/64 | l*64]
// ---------------------------------------------------------------------------
__global__ void prep_pool(const float* __restrict__ pool) {
    int p = blockIdx.x;
    int c = threadIdx.x;
    float v = pool[p * CCH + c];
    __shared__ float red[256];
    red[c] = v * v;
    __syncthreads();
    #pragma unroll
    for (int s = 128; s > 0; s >>= 1) {
        if (c < s) red[c] += red[c + s];
        __syncthreads();
    }
    float vn = v * (1.0f / sqrtf(red[0]));
    __half h  = __float2half(vn);
    float  hf = __half2float(h);
    __half l  = __float2half((vn - hf) * 64.0f);     // scaled residual (normal range)
    __half hs = __float2half(hf * 0.015625f);        // h / 64 (exact pow2 scale)
    __half* dst = g_B + (size_t)p * K3 + c;
    dst[0]   = h;
    dst[256] = hs;
    dst[512] = l;
}

// ---------------------------------------------------------------------------
// Kernel 2: per-pixel inverse norm of x.
// ---------------------------------------------------------------------------
__global__ void prep_xnorm(const float* __restrict__ x) {
    int idx = blockIdx.x * 256 + threadIdx.x;   // 0 .. 16383
    int n = idx >> 10, l = idx & (LL - 1);
    const float* xp = x + (size_t)n * CCH * LL + l;
    float s = 0.f;
    #pragma unroll 8
    for (int c = 0; c < CCH; c++) {
        float v = xp[c * LL];
        s = fmaf(v, v, s);
    }
    g_invxn[idx] = 1.0f / sqrtf(s);
}

// ---------------------------------------------------------------------------
// Kernel 3: transpose x [n][c][l] -> A' [n][l][K3] fp16 split [h | l*64 | h/64],
// with invxn folded in. 32x32 tiles, 256 threads.
// ---------------------------------------------------------------------------
__global__ __launch_bounds__(256) void prep_xT(const float* __restrict__ x) {
    int n  = blockIdx.z;
    int c0 = blockIdx.y * 32;
    int l0 = blockIdx.x * 32;
    int tx = threadIdx.x & 31;
    int ty = threadIdx.x >> 5;     // 0..7
    __shared__ float ss[32][33];

    const float* xp = x + (size_t)n * CCH * LL;
    #pragma unroll
    for (int i = 0; i < 4; i++) {
        int c = ty * 4 + i;
        ss[c][tx] = xp[(size_t)(c0 + c) * LL + l0 + tx];
    }
    __syncthreads();
    #pragma unroll
    for (int i = 0; i < 4; i++) {
        int lloc = ty * 4 + i;
        float s = g_invxn[n * LL + l0 + lloc];
        float v = ss[tx][lloc] * s;
        __half h  = __float2half(v);
        float  hf = __half2float(h);
        __half l  = __float2half((v - hf) * 64.0f);
        __half hs = __float2half(hf * 0.015625f);
        __half* dst = g_A + ((size_t)(n * LL + l0 + lloc)) * K3 + c0 + tx;
        dst[0]   = h;
        dst[256] = l;
        dst[512] = hs;
    }
}

// ---------------------------------------------------------------------------
// Kernel 4: HMMA GEMM via mma.sync.m16n8k16.f32.f16.f16.f32.
// CTA tile 128(l) x 128(p), 8 warps in 2x4 (warp tile 64x32),
// BK=64, cp.async double-buffered smem, stride 144 B (conflict-free).
// __launch_bounds__(256, 2): cap regs at 128 so 2 CTAs/SM co-reside
// (R9 profile: occ=12.5%, tensor=43% -> latency-bound at 8 warps/SM).
// ---------------------------------------------------------------------------
#define GBK    64
#define NCHUNK (K3 / GBK)          // 12
#define ASTRB  144                 // smem row stride in bytes (72 halves)
#define STAGE_BYTES (128 * ASTRB)  // 18432 per operand
#define SM_A_OFF(s) ((s) * 2 * STAGE_BYTES)
#define SM_B_OFF(s) ((s) * 2 * STAGE_BYTES + STAGE_BYTES)
#define SMEM_GEMM  (4 * STAGE_BYTES)   // 73728

__device__ __forceinline__ uint32_t smem_u32(const void* p) {
    uint32_t a;
    asm("{ .reg .u64 t; cvta.to.shared.u64 t, %1; cvt.u32.u64 %0, t; }" : "=r"(a) : "l"(p));
    return a;
}
#define CP16(sm_addr, gptr) \
    asm volatile("cp.async.cg.shared.global [%0], [%1], 16;" :: "r"(sm_addr), "l"(gptr) : "memory")
#define CP_COMMIT() asm volatile("cp.async.commit_group;" ::: "memory")
#define CP_WAIT(N)  asm volatile("cp.async.wait_group %0;" :: "n"(N) : "memory")

__device__ __forceinline__ void mma_fp16(float* c, const uint32_t* a, const uint32_t* b) {
    asm volatile(
        "mma.sync.aligned.m16n8k16.row.col.f32.f16.f16.f32 "
        "{%0,%1,%2,%3}, {%4,%5,%6,%7}, {%8,%9}, {%0,%1,%2,%3};"
        : "+f"(c[0]), "+f"(c[1]), "+f"(c[2]), "+f"(c[3])
        : "r"(a[0]), "r"(a[1]), "r"(a[2]), "r"(a[3]), "r"(b[0]), "r"(b[1]));
}

__global__ __launch_bounds__(256, 2) void gemm_mma() {
    extern __shared__ __align__(1024) char sm[];
    uint32_t smb = smem_u32(sm);

    int tid  = threadIdx.x;
    int lane = tid & 31;
    int warp = tid >> 5;
    int wm   = warp & 1;        // 0..1  (M half, 64 rows)
    int wn   = warp >> 1;       // 0..3  (N quarter, 32 cols)

    int n    = blockIdx.z;
    int pBlk = blockIdx.x * 128;
    int lBlk = blockIdx.y * 128;

    const __half* Ag = g_A + ((size_t)(n * LL + lBlk)) * K3;
    const __half* Bg = g_B + (size_t)pBlk * K3;

    #define LOADCHUNK(KC, S)                                                     \
    {                                                                            \
        int kc_ = (KC);                                                          \
        uint32_t sa = smb + SM_A_OFF(S);                                         \
        uint32_t sb = smb + SM_B_OFF(S);                                         \
        _Pragma("unroll")                                                        \
        for (int j = 0; j < 4; j++) {                                            \
            int u = tid + j * 256;                                               \
            int row = u >> 3, seg = u & 7;                                       \
            CP16(sa + row * ASTRB + seg * 16,                                    \
                 Ag + (size_t)row * K3 + kc_ * GBK + seg * 8);                   \
        }                                                                        \
        _Pragma("unroll")                                                        \
        for (int j = 0; j < 4; j++) {                                            \
            int u = tid + j * 256;                                               \
            int row = u >> 3, seg = u & 7;                                       \
            CP16(sb + row * ASTRB + seg * 16,                                    \
                 Bg + (size_t)row * K3 + kc_ * GBK + seg * 8);                   \
        }                                                                        \
    }

    float acc[4][4][4];
    #pragma unroll
    for (int i = 0; i < 4; i++)
        #pragma unroll
        for (int j = 0; j < 4; j++)
            #pragma unroll
            for (int q = 0; q < 4; q++) acc[i][j][q] = 0.f;

    int r  = lane >> 2;        // 0..7
    int cq = lane & 3;         // 0..3

    LOADCHUNK(0, 0);
    CP_COMMIT();

    #pragma unroll 1
    for (int kc = 0; kc < NCHUNK; kc++) {
        if (kc < NCHUNK - 1) {
            LOADCHUNK(kc + 1, (kc + 1) & 1);
            CP_COMMIT();
            CP_WAIT(1);
        } else {
            CP_WAIT(0);
        }
        __syncthreads();

        const char* As = sm + SM_A_OFF(kc & 1);
        const char* Bs = sm + SM_B_OFF(kc & 1);

        #pragma unroll
        for (int ks = 0; ks < GBK / 16; ks++) {
            int kb = ks * 32 + cq * 4;      // byte offset of this thread's k-pair
            uint32_t a[4][4], b[4][2];
            #pragma unroll
            for (int mt = 0; mt < 4; mt++) {
                const char* base = As + (wm * 64 + mt * 16 + r) * ASTRB + kb;
                a[mt][0] = *(const uint32_t*)(base);
                a[mt][1] = *(const uint32_t*)(base + 8 * ASTRB);
                a[mt][2] = *(const uint32_t*)(base + 16);
                a[mt][3] = *(const uint32_t*)(base + 8 * ASTRB + 16);
            }
            #pragma unroll
            for (int nt = 0; nt < 4; nt++) {
                const char* base = Bs + (wn * 32 + nt * 8 + r) * ASTRB + kb;
                b[nt][0] = *(const uint32_t*)(base);
                b[nt][1] = *(const uint32_t*)(base + 16);
            }
            #pragma unroll
            for (int mt = 0; mt < 4; mt++)
                #pragma unroll
                for (int nt = 0; nt < 4; nt++)
                    mma_fp16(acc[mt][nt], a[mt], b[nt]);
        }
        __syncthreads();
    }

    // Epilogue: write g_cos[n][l][p]
    #pragma unroll
    for (int mt = 0; mt < 4; mt++) {
        int l0 = lBlk + wm * 64 + mt * 16 + r;
        float* row0 = g_cos + ((size_t)(n * LL + l0)) * PP + pBlk;
        float* row1 = g_cos + ((size_t)(n * LL + l0 + 8)) * PP + pBlk;
        #pragma unroll
        for (int nt = 0; nt < 4; nt++) {
            int p = wn * 32 + nt * 8 + cq * 2;
            float2 v0 = make_float2(acc[mt][nt][0], acc[mt][nt][1]);
            float2 v1 = make_float2(acc[mt][nt][2], acc[mt][nt][3]);
            *(float2*)&row0[p] = v0;
            *(float2*)&row1[p] = v1;
        }
    }
}

// ---------------------------------------------------------------------------
// Kernel 5: per-pixel exact top-102, two-phase:
//   Phase A: coarse binary search on |cos| until candidate count <= CAND_MAX
//            (typically ~6-9 iterations, vs fixed 30 before).
//   Phase B: collect candidates, exact rank by one broadcast-LDS sweep
//            (rank = #{key > mine} + index tiebreak), keep rank < 102.
// Rank-ordered output arrays -> deterministic sum order. Then sparse recon.
// ---------------------------------------------------------------------------
#define CAND_MAX 384
#define CAND_ARR 512
#define MAXIT    32

__global__ __launch_bounds__(256) void topk_recon(const float* __restrict__ pool,
                                                  float* __restrict__ out) {
    int blk = blockIdx.x;            // n*1024 + l
    int n = blk >> 10, l = blk & (LL - 1);
    const float* row = g_cos + (size_t)blk * PP;

    __shared__ float sv[PP];
    __shared__ int   cnt[MAXIT];
    __shared__ int   s_cnt;
    __shared__ float s_ckey[CAND_ARR];
    __shared__ int   s_cidx[CAND_ARR];
    __shared__ int   s_idx[KEEP];
    __shared__ float s_val[KEEP];
    __shared__ float s_invS;

    int tid = threadIdx.x;

    float4 r0 = *(const float4*)&row[tid * 4];
    float4 r1 = *(const float4*)&row[1024 + tid * 4];
    *(float4*)&sv[tid * 4]        = r0;
    *(float4*)&sv[1024 + tid * 4] = r1;

    float a0 = fabsf(r0.x), a1 = fabsf(r0.y), a2 = fabsf(r0.z), a3 = fabsf(r0.w);
    float a4 = fabsf(r1.x), a5 = fabsf(r1.y), a6 = fabsf(r1.z), a7 = fabsf(r1.w);

    if (tid < MAXIT) cnt[tid] = 0;
    if (tid == 0) s_cnt = 0;
    __syncthreads();

    // Phase A: shrink candidate set. Invariant: count(key >= lo) >= KEEP.
    unsigned lo = 0u, hi = 0x3FC00000u;
    int cntLo = PP;
    int it = 0;
    while (cntLo > CAND_MAX && it < MAXIT) {
        unsigned mid = (lo + hi) >> 1;
        float mf = __uint_as_float(mid);
        int c = (a0 >= mf) + (a1 >= mf) + (a2 >= mf) + (a3 >= mf)
              + (a4 >= mf) + (a5 >= mf) + (a6 >= mf) + (a7 >= mf);
        c = __reduce_add_sync(0xFFFFFFFFu, c);
        if ((tid & 31) == 0) atomicAdd(&cnt[it], c);
        __syncthreads();
        int cm = cnt[it];
        if (cm >= KEEP) { lo = mid; cntLo = cm; }
        else            { hi = mid; }
        it++;
    }
    float loF = __uint_as_float(lo);

    // Phase B1: collect candidates (key >= loF). Set is deterministic;
    // slot order is not (irrelevant — ranking fixes final order).
    #define CAND(AV, IDX)                                               \
        {                                                               \
            float av_ = (AV);                                           \
            if (av_ >= loF) {                                           \
                int slot = atomicAdd(&s_cnt, 1);                        \
                if (slot < CAND_ARR) {                                  \
                    s_ckey[slot] = av_; s_cidx[slot] = (IDX);           \
                }                                                       \
            }                                                           \
        }
    int base = tid * 4;
    CAND(a0, base + 0)
    CAND(a1, base + 1)
    CAND(a2, base + 2)
    CAND(a3, base + 3)
    CAND(a4, 1024 + base + 0)
    CAND(a5, 1024 + base + 1)
    CAND(a6, 1024 + base + 2)
    CAND(a7, 1024 + base + 3)
    #undef CAND
    __syncthreads();

    int C = s_cnt;
    if (C > CAND_ARR) C = CAND_ARR;   // safety (unreachable with real data)

    // Phase B2: exact rank per candidate (broadcast LDS sweep, no barriers).
    for (int i = tid; i < C; i += 256) {
        float ki = s_ckey[i];
        int   ii = s_cidx[i];
        int rank = 0;
        #pragma unroll 4
        for (int j = 0; j < C; j++) {
            float kj = s_ckey[j];
            int   ij = s_cidx[j];
            rank += (kj > ki) | ((kj == ki) & (ij < ii));
        }
        if (rank < KEEP) {
            s_idx[rank] = ii;
            s_val[rank] = sv[ii];
        }
    }
    __syncthreads();

    if (tid == 0) {
        float z0 = 0.f, z1 = 0.f, z2 = 0.f, z3 = 0.f;
        int j = 0;
        for (; j + 4 <= KEEP; j += 4) {
            z0 += s_val[j]; z1 += s_val[j + 1];
            z2 += s_val[j + 2]; z3 += s_val[j + 3];
        }
        for (; j < KEEP; j++) z0 += s_val[j];
        s_invS = 1.0f / (z0 + z1 + z2 + z3);
    }
    __syncthreads();

    // Sparse reconstruction: thread owns channel c = tid; pool L2-resident.
    float acc = 0.f;
    #pragma unroll 6
    for (int j = 0; j < KEEP; j++) {
        acc = fmaf(s_val[j], __ldg(&pool[(size_t)s_idx[j] * CCH + tid]), acc);
    }
    out[(size_t)n * CCH * LL + (size_t)tid * LL + l] = acc * s_invS;
}

// ---------------------------------------------------------------------------
// Launch
// ---------------------------------------------------------------------------
extern "C" void kernel_launch(void* const* d_in, const int* in_sizes, int n_in,
                              void* d_out, int out_size) {
    const float* x    = (const float*)d_in[0];  // [16, 256, 32, 32]
    const float* pool = (const float*)d_in[1];  // [2048, 256]
    float* out        = (float*)d_out;          // [16, 256, 32, 32]

    cudaFuncSetAttribute(gemm_mma, cudaFuncAttributeMaxDynamicSharedMemorySize, SMEM_GEMM);

    prep_pool<<<PP, 256>>>(pool);
    prep_xnorm<<<(NB * LL) / 256, 256>>>(x);
    prep_xT<<<dim3(LL / 32, CCH / 32, NB), 256>>>(x);
    gemm_mma<<<dim3(PP / 128, LL / 128, NB), 256, SMEM_GEMM>>>();
    topk_recon<<<NB * LL, 256>>>(pool, out);
}

// round 11
// speedup vs baseline: 1.3956x; 1.3956x over previous
#include <cuda_runtime.h>
#include <cuda_fp16.h>
#include <math.h>
#include <stdint.h>

// Shapes (fixed by the problem)
#define NB   16
#define CCH  256
#define HH   32
#define WW   32
#define LL   (HH*WW)       // 1024
#define PP   2048
#define KEEP 102           // int(0.05 * 2048)
#define K3   768           // 3x fp16 split K (h | l*64 | h/64) . (h | h/64 | l*64)

// ---------------------------------------------------------------------------
// Scratch (device globals only; no allocations allowed)
// ---------------------------------------------------------------------------
__device__ float  g_invxn[NB * LL];                    // 64 KB
__device__ __half g_A[(size_t)NB * LL * K3];           // 25 MB  A' split of x^T * invxn
__device__ __half g_B[(size_t)PP * K3];                // 3 MB   B' split of poolN
__device__ float  g_cos[(size_t)NB * LL * PP];         // 134 MB

// ---------------------------------------------------------------------------
// Kernel 1: normalize pool rows, write fp16 split B' = [h | h/64 | l*64]
// ---------------------------------------------------------------------------
__global__ void prep_pool(const float* __restrict__ pool) {
    int p = blockIdx.x;
    int c = threadIdx.x;
    float v = pool[p * CCH + c];
    __shared__ float red[256];
    red[c] = v * v;
    __syncthreads();
    #pragma unroll
    for (int s = 128; s > 0; s >>= 1) {
        if (c < s) red[c] += red[c + s];
        __syncthreads();
    }
    float vn = v * (1.0f / sqrtf(red[0]));
    __half h  = __float2half(vn);
    float  hf = __half2float(h);
    __half l  = __float2half((vn - hf) * 64.0f);     // scaled residual (normal range)
    __half hs = __float2half(hf * 0.015625f);        // h / 64 (exact pow2 scale)
    __half* dst = g_B + (size_t)p * K3 + c;
    dst[0]   = h;
    dst[256] = hs;
    dst[512] = l;
}

// ---------------------------------------------------------------------------
// Kernel 2: per-pixel inverse norm of x.
// ---------------------------------------------------------------------------
__global__ void prep_xnorm(const float* __restrict__ x) {
    int idx = blockIdx.x * 256 + threadIdx.x;   // 0 .. 16383
    int n = idx >> 10, l = idx & (LL - 1);
    const float* xp = x + (size_t)n * CCH * LL + l;
    float s = 0.f;
    #pragma unroll 8
    for (int c = 0; c < CCH; c++) {
        float v = xp[c * LL];
        s = fmaf(v, v, s);
    }
    g_invxn[idx] = 1.0f / sqrtf(s);
}

// ---------------------------------------------------------------------------
// Kernel 3: transpose x [n][c][l] -> A' [n][l][K3] fp16 split [h | l*64 | h/64],
// with invxn folded in. 32x32 tiles, 256 threads.
// ---------------------------------------------------------------------------
__global__ __launch_bounds__(256) void prep_xT(const float* __restrict__ x) {
    int n  = blockIdx.z;
    int c0 = blockIdx.y * 32;
    int l0 = blockIdx.x * 32;
    int tx = threadIdx.x & 31;
    int ty = threadIdx.x >> 5;     // 0..7
    __shared__ float ss[32][33];

    const float* xp = x + (size_t)n * CCH * LL;
    #pragma unroll
    for (int i = 0; i < 4; i++) {
        int c = ty * 4 + i;
        ss[c][tx] = xp[(size_t)(c0 + c) * LL + l0 + tx];
    }
    __syncthreads();
    #pragma unroll
    for (int i = 0; i < 4; i++) {
        int lloc = ty * 4 + i;
        float s = g_invxn[n * LL + l0 + lloc];
        float v = ss[tx][lloc] * s;
        __half h  = __float2half(v);
        float  hf = __half2float(h);
        __half l  = __float2half((v - hf) * 64.0f);
        __half hs = __float2half(hf * 0.015625f);
        __half* dst = g_A + ((size_t)(n * LL + l0 + lloc)) * K3 + c0 + tx;
        dst[0]   = h;
        dst[256] = l;
        dst[512] = hs;
    }
}

// ---------------------------------------------------------------------------
// Kernel 4: HMMA GEMM via mma.sync.m16n8k16.f32.f16.f16.f32.
// CTA tile 128(l) x 128(p), 8 warps in 2x4 (warp tile 64x32),
// BK=64, cp.async double-buffered smem, stride 144 B (conflict-free),
// __launch_bounds__(256, 2) for 2 CTAs/SM. (R10: 169us, tensor=50%.)
// ---------------------------------------------------------------------------
#define GBK    64
#define NCHUNK (K3 / GBK)          // 12
#define ASTRB  144                 // smem row stride in bytes (72 halves)
#define STAGE_BYTES (128 * ASTRB)  // 18432 per operand
#define SM_A_OFF(s) ((s) * 2 * STAGE_BYTES)
#define SM_B_OFF(s) ((s) * 2 * STAGE_BYTES + STAGE_BYTES)
#define SMEM_GEMM  (4 * STAGE_BYTES)   // 73728

__device__ __forceinline__ uint32_t smem_u32(const void* p) {
    uint32_t a;
    asm("{ .reg .u64 t; cvta.to.shared.u64 t, %1; cvt.u32.u64 %0, t; }" : "=r"(a) : "l"(p));
    return a;
}
#define CP16(sm_addr, gptr) \
    asm volatile("cp.async.cg.shared.global [%0], [%1], 16;" :: "r"(sm_addr), "l"(gptr) : "memory")
#define CP_COMMIT() asm volatile("cp.async.commit_group;" ::: "memory")
#define CP_WAIT(N)  asm volatile("cp.async.wait_group %0;" :: "n"(N) : "memory")

__device__ __forceinline__ void mma_fp16(float* c, const uint32_t* a, const uint32_t* b) {
    asm volatile(
        "mma.sync.aligned.m16n8k16.row.col.f32.f16.f16.f32 "
        "{%0,%1,%2,%3}, {%4,%5,%6,%7}, {%8,%9}, {%0,%1,%2,%3};"
        : "+f"(c[0]), "+f"(c[1]), "+f"(c[2]), "+f"(c[3])
        : "r"(a[0]), "r"(a[1]), "r"(a[2]), "r"(a[3]), "r"(b[0]), "r"(b[1]));
}

__global__ __launch_bounds__(256, 2) void gemm_mma() {
    extern __shared__ __align__(1024) char sm[];
    uint32_t smb = smem_u32(sm);

    int tid  = threadIdx.x;
    int lane = tid & 31;
    int warp = tid >> 5;
    int wm   = warp & 1;        // 0..1  (M half, 64 rows)
    int wn   = warp >> 1;       // 0..3  (N quarter, 32 cols)

    int n    = blockIdx.z;
    int pBlk = blockIdx.x * 128;
    int lBlk = blockIdx.y * 128;

    const __half* Ag = g_A + ((size_t)(n * LL + lBlk)) * K3;
    const __half* Bg = g_B + (size_t)pBlk * K3;

    #define LOADCHUNK(KC, S)                                                     \
    {                                                                            \
        int kc_ = (KC);                                                          \
        uint32_t sa = smb + SM_A_OFF(S);                                         \
        uint32_t sb = smb + SM_B_OFF(S);                                         \
        _Pragma("unroll")                                                        \
        for (int j = 0; j < 4; j++) {                                            \
            int u = tid + j * 256;                                               \
            int row = u >> 3, seg = u & 7;                                       \
            CP16(sa + row * ASTRB + seg * 16,                                    \
                 Ag + (size_t)row * K3 + kc_ * GBK + seg * 8);                   \
        }                                                                        \
        _Pragma("unroll")                                                        \
        for (int j = 0; j < 4; j++) {                                            \
            int u = tid + j * 256;                                               \
            int row = u >> 3, seg = u & 7;                                       \
            CP16(sb + row * ASTRB + seg * 16,                                    \
                 Bg + (size_t)row * K3 + kc_ * GBK + seg * 8);                   \
        }                                                                        \
    }

    float acc[4][4][4];
    #pragma unroll
    for (int i = 0; i < 4; i++)
        #pragma unroll
        for (int j = 0; j < 4; j++)
            #pragma unroll
            for (int q = 0; q < 4; q++) acc[i][j][q] = 0.f;

    int r  = lane >> 2;        // 0..7
    int cq = lane & 3;         // 0..3

    LOADCHUNK(0, 0);
    CP_COMMIT();

    #pragma unroll 1
    for (int kc = 0; kc < NCHUNK; kc++) {
        if (kc < NCHUNK - 1) {
            LOADCHUNK(kc + 1, (kc + 1) & 1);
            CP_COMMIT();
            CP_WAIT(1);
        } else {
            CP_WAIT(0);
        }
        __syncthreads();

        const char* As = sm + SM_A_OFF(kc & 1);
        const char* Bs = sm + SM_B_OFF(kc & 1);

        #pragma unroll
        for (int ks = 0; ks < GBK / 16; ks++) {
            int kb = ks * 32 + cq * 4;      // byte offset of this thread's k-pair
            uint32_t a[4][4], b[4][2];
            #pragma unroll
            for (int mt = 0; mt < 4; mt++) {
                const char* base = As + (wm * 64 + mt * 16 + r) * ASTRB + kb;
                a[mt][0] = *(const uint32_t*)(base);
                a[mt][1] = *(const uint32_t*)(base + 8 * ASTRB);
                a[mt][2] = *(const uint32_t*)(base + 16);
                a[mt][3] = *(const uint32_t*)(base + 8 * ASTRB + 16);
            }
            #pragma unroll
            for (int nt = 0; nt < 4; nt++) {
                const char* base = Bs + (wn * 32 + nt * 8 + r) * ASTRB + kb;
                b[nt][0] = *(const uint32_t*)(base);
                b[nt][1] = *(const uint32_t*)(base + 16);
            }
            #pragma unroll
            for (int mt = 0; mt < 4; mt++)
                #pragma unroll
                for (int nt = 0; nt < 4; nt++)
                    mma_fp16(acc[mt][nt], a[mt], b[nt]);
        }
        __syncthreads();
    }

    // Epilogue: write g_cos[n][l][p]
    #pragma unroll
    for (int mt = 0; mt < 4; mt++) {
        int l0 = lBlk + wm * 64 + mt * 16 + r;
        float* row0 = g_cos + ((size_t)(n * LL + l0)) * PP + pBlk;
        float* row1 = g_cos + ((size_t)(n * LL + l0 + 8)) * PP + pBlk;
        #pragma unroll
        for (int nt = 0; nt < 4; nt++) {
            int p = wn * 32 + nt * 8 + cq * 2;
            float2 v0 = make_float2(acc[mt][nt][0], acc[mt][nt][1]);
            float2 v1 = make_float2(acc[mt][nt][2], acc[mt][nt][3]);
            *(float2*)&row0[p] = v0;
            *(float2*)&row1[p] = v1;
        }
    }
}

// ---------------------------------------------------------------------------
// Kernel 5: per-pixel exact top-102, two-phase.
//   Phase A: binary search on |cos| until candidate count <= CAND_MAX.
//   Phase B: collect candidates, exact rank via broadcast-LDS sweep.
// R10 lesson: rank cost is O(C^2) while search savings are O(log C) —
// CAND_MAX=384 made rank dominate (+170us). CAND_MAX=150 puts the
// crossover right: ~12 search rounds + ~150-iteration rank sweep.
// ---------------------------------------------------------------------------
#define CAND_MAX 150
#define CAND_ARR 320
#define MAXIT    32

__global__ __launch_bounds__(256) void topk_recon(const float* __restrict__ pool,
                                                  float* __restrict__ out) {
    int blk = blockIdx.x;            // n*1024 + l
    int n = blk >> 10, l = blk & (LL - 1);
    const float* row = g_cos + (size_t)blk * PP;

    __shared__ float sv[PP];
    __shared__ int   cnt[MAXIT];
    __shared__ int   s_cnt;
    __shared__ float s_ckey[CAND_ARR];
    __shared__ int   s_cidx[CAND_ARR];
    __shared__ int   s_idx[KEEP];
    __shared__ float s_val[KEEP];
    __shared__ float s_invS;

    int tid = threadIdx.x;

    float4 r0 = *(const float4*)&row[tid * 4];
    float4 r1 = *(const float4*)&row[1024 + tid * 4];
    *(float4*)&sv[tid * 4]        = r0;
    *(float4*)&sv[1024 + tid * 4] = r1;

    float a0 = fabsf(r0.x), a1 = fabsf(r0.y), a2 = fabsf(r0.z), a3 = fabsf(r0.w);
    float a4 = fabsf(r1.x), a5 = fabsf(r1.y), a6 = fabsf(r1.z), a7 = fabsf(r1.w);

    if (tid < MAXIT) cnt[tid] = 0;
    if (tid == 0) s_cnt = 0;
    __syncthreads();

    // Phase A: shrink candidate set. Invariant: count(key >= lo) >= KEEP.
    unsigned lo = 0u, hi = 0x3FC00000u;
    int cntLo = PP;
    int it = 0;
    while (cntLo > CAND_MAX && it < MAXIT) {
        unsigned mid = (lo + hi) >> 1;
        float mf = __uint_as_float(mid);
        int c = (a0 >= mf) + (a1 >= mf) + (a2 >= mf) + (a3 >= mf)
              + (a4 >= mf) + (a5 >= mf) + (a6 >= mf) + (a7 >= mf);
        c = __reduce_add_sync(0xFFFFFFFFu, c);
        if ((tid & 31) == 0) atomicAdd(&cnt[it], c);
        __syncthreads();
        int cm = cnt[it];
        if (cm >= KEEP) { lo = mid; cntLo = cm; }
        else            { hi = mid; }
        it++;
    }
    float loF = __uint_as_float(lo);

    // Phase B1: collect candidates (key >= loF). Set is deterministic;
    // slot order is not (irrelevant — ranking fixes final order).
    #define CAND(AV, IDX)                                               \
        {                                                               \
            float av_ = (AV);                                           \
            if (av_ >= loF) {                                           \
                int slot = atomicAdd(&s_cnt, 1);                        \
                if (slot < CAND_ARR) {                                  \
                    s_ckey[slot] = av_; s_cidx[slot] = (IDX);           \
                }                                                       \
            }                                                           \
        }
    int base = tid * 4;
    CAND(a0, base + 0)
    CAND(a1, base + 1)
    CAND(a2, base + 2)
    CAND(a3, base + 3)
    CAND(a4, 1024 + base + 0)
    CAND(a5, 1024 + base + 1)
    CAND(a6, 1024 + base + 2)
    CAND(a7, 1024 + base + 3)
    #undef CAND
    __syncthreads();

    int C = s_cnt;
    if (C > CAND_ARR) C = CAND_ARR;   // safety (unreachable with real data)

    // Phase B2: exact rank per candidate (broadcast LDS sweep, no barriers).
    for (int i = tid; i < C; i += 256) {
        float ki = s_ckey[i];
        int   ii = s_cidx[i];
        int rank = 0;
        #pragma unroll 4
        for (int j = 0; j < C; j++) {
            float kj = s_ckey[j];
            int   ij = s_cidx[j];
            rank += (kj > ki) | ((kj == ki) & (ij < ii));
        }
        if (rank < KEEP) {
            s_idx[rank] = ii;
            s_val[rank] = sv[ii];
        }
    }
    __syncthreads();

    if (tid == 0) {
        float z0 = 0.f, z1 = 0.f, z2 = 0.f, z3 = 0.f;
        int j = 0;
        for (; j + 4 <= KEEP; j += 4) {
            z0 += s_val[j]; z1 += s_val[j + 1];
            z2 += s_val[j + 2]; z3 += s_val[j + 3];
        }
        for (; j < KEEP; j++) z0 += s_val[j];
        s_invS = 1.0f / (z0 + z1 + z2 + z3);
    }
    __syncthreads();

    // Sparse reconstruction: thread owns channel c = tid; pool L2-resident.
    float acc = 0.f;
    #pragma unroll 6
    for (int j = 0; j < KEEP; j++) {
        acc = fmaf(s_val[j], __ldg(&pool[(size_t)s_idx[j] * CCH + tid]), acc);
    }
    out[(size_t)n * CCH * LL + (size_t)tid * LL + l] = acc * s_invS;
}

// ---------------------------------------------------------------------------
// Launch
// ---------------------------------------------------------------------------
extern "C" void kernel_launch(void* const* d_in, const int* in_sizes, int n_in,
                              void* d_out, int out_size) {
    const float* x    = (const float*)d_in[0];  // [16, 256, 32, 32]
    const float* pool = (const float*)d_in[1];  // [2048, 256]
    float* out        = (float*)d_out;          // [16, 256, 32, 32]

    cudaFuncSetAttribute(gemm_mma, cudaFuncAttributeMaxDynamicSharedMemorySize, SMEM_GEMM);

    prep_pool<<<PP, 256>>>(pool);
    prep_xnorm<<<(NB * LL) / 256, 256>>>(x);
    prep_xT<<<dim3(LL / 32, CCH / 32, NB), 256>>>(x);
    gemm_mma<<<dim3(PP / 128, LL / 128, NB), 256, SMEM_GEMM>>>();
    topk_recon<<<NB * LL, 256>>>(pool, out);
}

// round 12
// speedup vs baseline: 1.6323x; 1.1696x over previous
#include <cuda_runtime.h>
#include <cuda_fp16.h>
#include <math.h>
#include <stdint.h>

// Shapes (fixed by the problem)
#define NB   16
#define CCH  256
#define HH   32
#define WW   32
#define LL   (HH*WW)       // 1024
#define PP   2048
#define KEEP 102           // int(0.05 * 2048)
#define K3   768           // 3x fp16 split K (h | l*64 | h/64) . (h | h/64 | l*64)

// ---------------------------------------------------------------------------
// Scratch (device globals only; no allocations allowed)
// ---------------------------------------------------------------------------
__device__ float  g_invxn[NB * LL];                    // 64 KB
__device__ __half g_A[(size_t)NB * LL * K3];           // 25 MB  A' split of x^T * invxn
__device__ __half g_B[(size_t)PP * K3];                // 3 MB   B' split of poolN
__device__ float  g_cos[(size_t)NB * LL * PP];         // 134 MB

// ---------------------------------------------------------------------------
// Kernel 1: normalize pool rows, write fp16 split B' = [h | h/64 | l*64]
// ---------------------------------------------------------------------------
__global__ void prep_pool(const float* __restrict__ pool) {
    int p = blockIdx.x;
    int c = threadIdx.x;
    float v = pool[p * CCH + c];
    __shared__ float red[256];
    red[c] = v * v;
    __syncthreads();
    #pragma unroll
    for (int s = 128; s > 0; s >>= 1) {
        if (c < s) red[c] += red[c + s];
        __syncthreads();
    }
    float vn = v * (1.0f / sqrtf(red[0]));
    __half h  = __float2half(vn);
    float  hf = __half2float(h);
    __half l  = __float2half((vn - hf) * 64.0f);     // scaled residual (normal range)
    __half hs = __float2half(hf * 0.015625f);        // h / 64 (exact pow2 scale)
    __half* dst = g_B + (size_t)p * K3 + c;
    dst[0]   = h;
    dst[256] = hs;
    dst[512] = l;
}

// ---------------------------------------------------------------------------
// Kernel 2: per-pixel inverse norm of x.
// ---------------------------------------------------------------------------
__global__ void prep_xnorm(const float* __restrict__ x) {
    int idx = blockIdx.x * 256 + threadIdx.x;   // 0 .. 16383
    int n = idx >> 10, l = idx & (LL - 1);
    const float* xp = x + (size_t)n * CCH * LL + l;
    float s = 0.f;
    #pragma unroll 8
    for (int c = 0; c < CCH; c++) {
        float v = xp[c * LL];
        s = fmaf(v, v, s);
    }
    g_invxn[idx] = 1.0f / sqrtf(s);
}

// ---------------------------------------------------------------------------
// Kernel 3: transpose x [n][c][l] -> A' [n][l][K3] fp16 split [h | l*64 | h/64],
// with invxn folded in. 32x32 tiles, 256 threads.
// ---------------------------------------------------------------------------
__global__ __launch_bounds__(256) void prep_xT(const float* __restrict__ x) {
    int n  = blockIdx.z;
    int c0 = blockIdx.y * 32;
    int l0 = blockIdx.x * 32;
    int tx = threadIdx.x & 31;
    int ty = threadIdx.x >> 5;     // 0..7
    __shared__ float ss[32][33];

    const float* xp = x + (size_t)n * CCH * LL;
    #pragma unroll
    for (int i = 0; i < 4; i++) {
        int c = ty * 4 + i;
        ss[c][tx] = xp[(size_t)(c0 + c) * LL + l0 + tx];
    }
    __syncthreads();
    #pragma unroll
    for (int i = 0; i < 4; i++) {
        int lloc = ty * 4 + i;
        float s = g_invxn[n * LL + l0 + lloc];
        float v = ss[tx][lloc] * s;
        __half h  = __float2half(v);
        float  hf = __half2float(h);
        __half l  = __float2half((v - hf) * 64.0f);
        __half hs = __float2half(hf * 0.015625f);
        __half* dst = g_A + ((size_t)(n * LL + l0 + lloc)) * K3 + c0 + tx;
        dst[0]   = h;
        dst[256] = l;
        dst[512] = hs;
    }
}

// ---------------------------------------------------------------------------
// Kernel 4: HMMA GEMM via mma.sync + ldmatrix fragment loads.
// CTA tile 128(l) x 128(p), 8 warps in 2x4 (warp tile 64x32),
// BK=64, cp.async double-buffered smem, stride 144 B (conflict-free),
// 2 CTAs/SM. R11 profile: issue-throttled by 24 scalar LDS per k-step;
// ldmatrix x4 cuts that to 6 LDSM per k-step (1920 -> 1056 warp-instrs).
// ---------------------------------------------------------------------------
#define GBK    64
#define NCHUNK (K3 / GBK)          // 12
#define ASTRB  144                 // smem row stride in bytes (72 halves)
#define STAGE_BYTES (128 * ASTRB)  // 18432 per operand
#define SM_A_OFF(s) ((s) * 2 * STAGE_BYTES)
#define SM_B_OFF(s) ((s) * 2 * STAGE_BYTES + STAGE_BYTES)
#define SMEM_GEMM  (4 * STAGE_BYTES)   // 73728

__device__ __forceinline__ uint32_t smem_u32(const void* p) {
    uint32_t a;
    asm("{ .reg .u64 t; cvta.to.shared.u64 t, %1; cvt.u32.u64 %0, t; }" : "=r"(a) : "l"(p));
    return a;
}
#define CP16(sm_addr, gptr) \
    asm volatile("cp.async.cg.shared.global [%0], [%1], 16;" :: "r"(sm_addr), "l"(gptr) : "memory")
#define CP_COMMIT() asm volatile("cp.async.commit_group;" ::: "memory")
#define CP_WAIT(N)  asm volatile("cp.async.wait_group %0;" :: "n"(N) : "memory")

#define LDSM4(R0, R1, R2, R3, ADDR) \
    asm volatile("ldmatrix.sync.aligned.m8n8.x4.shared.b16 {%0,%1,%2,%3}, [%4];" \
        : "=r"(R0), "=r"(R1), "=r"(R2), "=r"(R3) : "r"(ADDR))

__device__ __forceinline__ void mma_fp16(float* c, const uint32_t* a,
                                         uint32_t b0, uint32_t b1) {
    asm volatile(
        "mma.sync.aligned.m16n8k16.row.col.f32.f16.f16.f32 "
        "{%0,%1,%2,%3}, {%4,%5,%6,%7}, {%8,%9}, {%0,%1,%2,%3};"
        : "+f"(c[0]), "+f"(c[1]), "+f"(c[2]), "+f"(c[3])
        : "r"(a[0]), "r"(a[1]), "r"(a[2]), "r"(a[3]), "r"(b0), "r"(b1));
}

__global__ __launch_bounds__(256, 2) void gemm_mma() {
    extern __shared__ __align__(1024) char sm[];
    uint32_t smb = smem_u32(sm);

    int tid  = threadIdx.x;
    int lane = tid & 31;
    int warp = tid >> 5;
    int wm   = warp & 1;        // 0..1  (M half, 64 rows)
    int wn   = warp >> 1;       // 0..3  (N quarter, 32 cols)

    int n    = blockIdx.z;
    int pBlk = blockIdx.x * 128;
    int lBlk = blockIdx.y * 128;

    const __half* Ag = g_A + ((size_t)(n * LL + lBlk)) * K3;
    const __half* Bg = g_B + (size_t)pBlk * K3;

    #define LOADCHUNK(KC, S)                                                     \
    {                                                                            \
        int kc_ = (KC);                                                          \
        uint32_t sa = smb + SM_A_OFF(S);                                         \
        uint32_t sb = smb + SM_B_OFF(S);                                         \
        _Pragma("unroll")                                                        \
        for (int j = 0; j < 4; j++) {                                            \
            int u = tid + j * 256;                                               \
            int row = u >> 3, seg = u & 7;                                       \
            CP16(sa + row * ASTRB + seg * 16,                                    \
                 Ag + (size_t)row * K3 + kc_ * GBK + seg * 8);                   \
        }                                                                        \
        _Pragma("unroll")                                                        \
        for (int j = 0; j < 4; j++) {                                            \
            int u = tid + j * 256;                                               \
            int row = u >> 3, seg = u & 7;                                       \
            CP16(sb + row * ASTRB + seg * 16,                                    \
                 Bg + (size_t)row * K3 + kc_ * GBK + seg * 8);                   \
        }                                                                        \
    }

    float acc[4][4][4];
    #pragma unroll
    for (int i = 0; i < 4; i++)
        #pragma unroll
        for (int j = 0; j < 4; j++)
            #pragma unroll
            for (int q = 0; q < 4; q++) acc[i][j][q] = 0.f;

    // ldmatrix lane-address decomposition.
    // A x4 (per mt): matrices {m0-7,k0-7},{m8-15,k0-7},{m0-7,k8-15},{m8-15,k8-15}
    //   -> regs a0..a3 == canonical m16n8k16 A fragment.
    // B x4 (per nt pair): {n-tile even k0-7},{even k8-15},{odd k0-7},{odd k8-15}
    //   -> regs == (b0,b1) of nt even then nt odd.
    int lrow = lane & 7;
    int lm   = lane >> 3;   // 0..3
    uint32_t aOff = (uint32_t)((wm * 64 + (lm & 1) * 8 + lrow) * ASTRB + (lm >> 1) * 16);
    uint32_t bOff = (uint32_t)((wn * 32 + (lm >> 1) * 8 + lrow) * ASTRB + (lm & 1) * 16);

    LOADCHUNK(0, 0);
    CP_COMMIT();

    #pragma unroll 1
    for (int kc = 0; kc < NCHUNK; kc++) {
        if (kc < NCHUNK - 1) {
            LOADCHUNK(kc + 1, (kc + 1) & 1);
            CP_COMMIT();
            CP_WAIT(1);
        } else {
            CP_WAIT(0);
        }
        __syncthreads();

        uint32_t sA = smb + SM_A_OFF(kc & 1) + aOff;
        uint32_t sB = smb + SM_B_OFF(kc & 1) + bOff;

        #pragma unroll
        for (int ks = 0; ks < GBK / 16; ks++) {
            uint32_t a[4][4], b[2][4];
            #pragma unroll
            for (int mt = 0; mt < 4; mt++)
                LDSM4(a[mt][0], a[mt][1], a[mt][2], a[mt][3],
                      sA + mt * (16 * ASTRB) + ks * 32);
            #pragma unroll
            for (int nt2 = 0; nt2 < 2; nt2++)
                LDSM4(b[nt2][0], b[nt2][1], b[nt2][2], b[nt2][3],
                      sB + nt2 * (16 * ASTRB) + ks * 32);
            #pragma unroll
            for (int mt = 0; mt < 4; mt++)
                #pragma unroll
                for (int nt = 0; nt < 4; nt++)
                    mma_fp16(acc[mt][nt], a[mt],
                             b[nt >> 1][(nt & 1) * 2], b[nt >> 1][(nt & 1) * 2 + 1]);
        }
        __syncthreads();
    }

    // Epilogue: write g_cos[n][l][p]
    int r  = lane >> 2;        // 0..7
    int cq = lane & 3;         // 0..3
    #pragma unroll
    for (int mt = 0; mt < 4; mt++) {
        int l0 = lBlk + wm * 64 + mt * 16 + r;
        float* row0 = g_cos + ((size_t)(n * LL + l0)) * PP + pBlk;
        float* row1 = g_cos + ((size_t)(n * LL + l0 + 8)) * PP + pBlk;
        #pragma unroll
        for (int nt = 0; nt < 4; nt++) {
            int p = wn * 32 + nt * 8 + cq * 2;
            float2 v0 = make_float2(acc[mt][nt][0], acc[mt][nt][1]);
            float2 v1 = make_float2(acc[mt][nt][2], acc[mt][nt][3]);
            *(float2*)&row0[p] = v0;
            *(float2*)&row1[p] = v1;
        }
    }
}

// ---------------------------------------------------------------------------
// Kernel 5: per-pixel exact top-102 (two-phase select) + sparse recon.
// Gather now uses float4 pool loads with the KEEP terms split across 4
// thread-groups (warp-LDG count per block 816 -> 208), combined via smem.
// ---------------------------------------------------------------------------
#define CAND_MAX 150
#define CAND_ARR 320
#define MAXIT    32

__global__ __launch_bounds__(256) void topk_recon(const float* __restrict__ pool,
                                                  float* __restrict__ out) {
    int blk = blockIdx.x;            // n*1024 + l
    int n = blk >> 10, l = blk & (LL - 1);
    const float* row = g_cos + (size_t)blk * PP;

    __shared__ float  sv[PP];
    __shared__ int    cnt[MAXIT];
    __shared__ int    s_cnt;
    __shared__ float  s_ckey[CAND_ARR];
    __shared__ int    s_cidx[CAND_ARR];
    __shared__ int    s_idx[KEEP];
    __shared__ float  s_val[KEEP];
    __shared__ float  s_invS;
    __shared__ float4 s_part[4][64];

    int tid = threadIdx.x;

    float4 r0 = *(const float4*)&row[tid * 4];
    float4 r1 = *(const float4*)&row[1024 + tid * 4];
    *(float4*)&sv[tid * 4]        = r0;
    *(float4*)&sv[1024 + tid * 4] = r1;

    float a0 = fabsf(r0.x), a1 = fabsf(r0.y), a2 = fabsf(r0.z), a3 = fabsf(r0.w);
    float a4 = fabsf(r1.x), a5 = fabsf(r1.y), a6 = fabsf(r1.z), a7 = fabsf(r1.w);

    if (tid < MAXIT) cnt[tid] = 0;
    if (tid == 0) s_cnt = 0;
    __syncthreads();

    // Phase A: shrink candidate set. Invariant: count(key >= lo) >= KEEP.
    unsigned lo = 0u, hi = 0x3FC00000u;
    int cntLo = PP;
    int it = 0;
    while (cntLo > CAND_MAX && it < MAXIT) {
        unsigned mid = (lo + hi) >> 1;
        float mf = __uint_as_float(mid);
        int c = (a0 >= mf) + (a1 >= mf) + (a2 >= mf) + (a3 >= mf)
              + (a4 >= mf) + (a5 >= mf) + (a6 >= mf) + (a7 >= mf);
        c = __reduce_add_sync(0xFFFFFFFFu, c);
        if ((tid & 31) == 0) atomicAdd(&cnt[it], c);
        __syncthreads();
        int cm = cnt[it];
        if (cm >= KEEP) { lo = mid; cntLo = cm; }
        else            { hi = mid; }
        it++;
    }
    float loF = __uint_as_float(lo);

    // Phase B1: collect candidates (key >= loF).
    #define CAND(AV, IDX)                                               \
        {                                                               \
            float av_ = (AV);                                           \
            if (av_ >= loF) {                                           \
                int slot = atomicAdd(&s_cnt, 1);                        \
                if (slot < CAND_ARR) {                                  \
                    s_ckey[slot] = av_; s_cidx[slot] = (IDX);           \
                }                                                       \
            }                                                           \
        }
    int base = tid * 4;
    CAND(a0, base + 0)
    CAND(a1, base + 1)
    CAND(a2, base + 2)
    CAND(a3, base + 3)
    CAND(a4, 1024 + base + 0)
    CAND(a5, 1024 + base + 1)
    CAND(a6, 1024 + base + 2)
    CAND(a7, 1024 + base + 3)
    #undef CAND
    __syncthreads();

    int C = s_cnt;
    if (C > CAND_ARR) C = CAND_ARR;   // safety (unreachable with real data)

    // Phase B2: exact rank per candidate (broadcast LDS sweep, no barriers).
    for (int i = tid; i < C; i += 256) {
        float ki = s_ckey[i];
        int   ii = s_cidx[i];
        int rank = 0;
        #pragma unroll 4
        for (int j = 0; j < C; j++) {
            float kj = s_ckey[j];
            int   ij = s_cidx[j];
            rank += (kj > ki) | ((kj == ki) & (ij < ii));
        }
        if (rank < KEEP) {
            s_idx[rank] = ii;
            s_val[rank] = sv[ii];
        }
    }
    __syncthreads();

    if (tid == 0) {
        float z0 = 0.f, z1 = 0.f, z2 = 0.f, z3 = 0.f;
        int j = 0;
        for (; j + 4 <= KEEP; j += 4) {
            z0 += s_val[j]; z1 += s_val[j + 1];
            z2 += s_val[j + 2]; z3 += s_val[j + 3];
        }
        for (; j < KEEP; j++) z0 += s_val[j];
        s_invS = 1.0f / (z0 + z1 + z2 + z3);
    }
    __syncthreads();

    // Sparse reconstruction, float4 + j-split:
    // group g = tid>>6 handles keeps j == g (mod 4); thread covers channels
    // [4t, 4t+4), t = tid&63. Partials combined through smem (order fixed).
    {
        const float4* pool4 = (const float4*)pool;
        int g = tid >> 6;
        int t = tid & 63;
        float4 acc = make_float4(0.f, 0.f, 0.f, 0.f);
        #pragma unroll 4
        for (int j = g; j < KEEP; j += 4) {
            float  w  = s_val[j];
            float4 pv = __ldg(&pool4[(size_t)s_idx[j] * 64 + t]);
            acc.x = fmaf(w, pv.x, acc.x);
            acc.y = fmaf(w, pv.y, acc.y);
            acc.z = fmaf(w, pv.z, acc.z);
            acc.w = fmaf(w, pv.w, acc.w);
        }
        s_part[g][t] = acc;
    }
    __syncthreads();

    {
        int t    = tid >> 2;        // 0..63
        int comp = tid & 3;         // 0..3  -> channel c = 4t+comp = tid
        float v = ((const float*)&s_part[0][t])[comp]
                + ((const float*)&s_part[1][t])[comp]
                + ((const float*)&s_part[2][t])[comp]
                + ((const float*)&s_part[3][t])[comp];
        out[(size_t)n * CCH * LL + (size_t)tid * LL + l] = v * s_invS;
    }
}

// ---------------------------------------------------------------------------
// Launch
// ---------------------------------------------------------------------------
extern "C" void kernel_launch(void* const* d_in, const int* in_sizes, int n_in,
                              void* d_out, int out_size) {
    const float* x    = (const float*)d_in[0];  // [16, 256, 32, 32]
    const float* pool = (const float*)d_in[1];  // [2048, 256]
    float* out        = (float*)d_out;          // [16, 256, 32, 32]

    cudaFuncSetAttribute(gemm_mma, cudaFuncAttributeMaxDynamicSharedMemorySize, SMEM_GEMM);

    prep_pool<<<PP, 256>>>(pool);
    prep_xnorm<<<(NB * LL) / 256, 256>>>(x);
    prep_xT<<<dim3(LL / 32, CCH / 32, NB), 256>>>(x);
    gemm_mma<<<dim3(PP / 128, LL / 128, NB), 256, SMEM_GEMM>>>();
    topk_recon<<<NB * LL, 256>>>(pool, out);
}